// round 9
// baseline (speedup 1.0000x reference)
#include <cuda_runtime.h>

// CRF NLL: B=1024, T=4096, K=16
// d_in[0]=feats [B,T,K] f32, d_in[1]=tags [B,T] i32, d_in[2]=transitions [K,K] f32
// out: [B] f32
//
// Shifted recurrence on the UNSCALED vector s_t = M alpha_{t-1}:
//   s_{t+1} = sum_i (Mr[i] * ef_t[i]) * s_t[i]
// ef_t (and the exact pow2 renorm scale) are exchanged one iteration ahead
// through a second smem buffer, so the scan chain is only sync->LDS->FMA->STS.
// One element per warp, lanes 16-31 mirror lanes 0-15 (idempotent stores).

#define T_LEN 4096
#define KTAG 16
#define TILE 8
#define START_TAG 14
#define STOP_TAG 15

__global__ __launch_bounds__(128, 2)
void crf_nll_kernel(const float* __restrict__ feats,
                    const int* __restrict__ tags,
                    const float* __restrict__ trans,
                    float* __restrict__ out) {
    __shared__ float sExpT[256];   // exp(trans[j][i])
    __shared__ float sLogT[256];   // trans[j][i]
    __shared__ float sS[4][16];    // raw scan vector s (one per warp)
    __shared__ float sEF[4][16];   // scaled ef, published one step ahead

    int tid = threadIdx.x;
    for (int i = tid; i < 256; i += 128) {
        float tv = trans[i];
        sLogT[i] = tv;
        sExpT[i] = __expf(tv);     // exp(-10000) -> 0: correct masking
    }

    int lane = tid & 31;
    int j    = lane & 15;          // owned state; upper half mirrors lower
    int warp = tid >> 5;
    int b    = blockIdx.x * 4 + warp;

    __syncthreads();

    float Mr[16];
    #pragma unroll
    for (int i = 0; i < 16; i++) Mr[i] = sExpT[j * 16 + i];
    float Mstop = sExpT[STOP_TAG * 16 + j];

    const float* fbase = feats + (size_t)b * T_LEN * KTAG;
    const int*   tptr  = tags  + (size_t)b * T_LEN;

    float* S  = &sS[warp][0];
    float* EF = &sEF[warp][0];

    S[j] = (j == START_TAG) ? 1.0f : 0.0f;    // s_0 = alpha_0 (prob domain)
    __syncthreads();

    // W for iteration 0 is plain Mr (alpha_1 = ef_0 .* (M alpha_0); the ef_0
    // factor enters via W at iteration 1).
    float W[16];
    #pragma unroll
    for (int i = 0; i < 16; i++) W[i] = Mr[i];

    int   esum = 0;           // exact pow2 scale accumulator
    float gold = 0.0f;
    int   prevtag = START_TAG;
    float pnew = 0.0f;
    float stale_m = 1.0f;     // max measured 2 iters before it is applied
    float ef_last = 1.0f;     // last published (scaled) ef, for the terminal

    float fA[TILE], fB[TILE];
    int   gA[TILE], gB[TILE];

    // prime first tile of raw feats + tags
    #pragma unroll
    for (int u = 0; u < TILE; u++) fA[u] = fbase[u * KTAG + j];
    {
        const int4* tp4 = reinterpret_cast<const int4*>(tptr);
        #pragma unroll
        for (int q = 0; q < TILE / 4; q++) {
            int4 v = tp4[q];
            gA[4*q+0] = v.x; gA[4*q+1] = v.y; gA[4*q+2] = v.z; gA[4*q+3] = v.w;
        }
    }

    // ef(feats[i]) is published at iteration i; computed one iter early.
    float efn = __expf(fA[0]);

    const int NT = T_LEN / TILE;   // 512
    #pragma unroll 1
    for (int tile = 0; tile < NT; tile++) {
        if (tile + 1 < NT) {
            int base = (tile + 1) * TILE;
            #pragma unroll
            for (int u = 0; u < TILE; u++) fB[u] = fbase[(base + u) * KTAG + j];
            const int4* tp4 = reinterpret_cast<const int4*>(tptr + base);
            #pragma unroll
            for (int q = 0; q < TILE / 4; q++) {
                int4 v = tp4[q];
                gB[4*q+0] = v.x; gB[4*q+1] = v.y; gB[4*q+2] = v.z; gB[4*q+3] = v.w;
            }
        }
        int tbase = tile * TILE;

        #pragma unroll
        for (int u = 0; u < TILE; u++) {
            int tg = gA[u];

            // publish (scaled) ef for the NEXT iteration's W
            float efs = efn;
            if ((u & 3) == 3) {    // fold exact pow2 renorm into published ef
                int e = (__float_as_int(stale_m) >> 23) & 255;
                efs *= __int_as_float((254 - e) << 23);   // * 2^(127-e), exact
                esum += e - 127;
            }
            EF[j] = efs;
            ef_last = efs;

            __syncwarp();
            // scan chain: LDS s quads -> FMA tree -> STS (nothing else)
            float4 q0 = *reinterpret_cast<const float4*>(S + 0);
            float4 q1 = *reinterpret_cast<const float4*>(S + 4);
            float4 q2 = *reinterpret_cast<const float4*>(S + 8);
            float4 q3 = *reinterpret_cast<const float4*>(S + 12);
            // ef vector for building next W (off-chain consumers)
            float4 e0 = *reinterpret_cast<const float4*>(EF + 0);
            float4 e1 = *reinterpret_cast<const float4*>(EF + 4);
            float4 e2 = *reinterpret_cast<const float4*>(EF + 8);
            float4 e3 = *reinterpret_cast<const float4*>(EF + 12);

            float a0 = fmaf(q3.x, W[12], fmaf(q2.x, W[ 8], fmaf(q1.x, W[4], q0.x * W[0])));
            float a1 = fmaf(q3.y, W[13], fmaf(q2.y, W[ 9], fmaf(q1.y, W[5], q0.y * W[1])));
            float a2 = fmaf(q3.z, W[14], fmaf(q2.z, W[10], fmaf(q1.z, W[6], q0.z * W[2])));
            float a3 = fmaf(q3.w, W[15], fmaf(q2.w, W[11], fmaf(q1.w, W[7], q0.w * W[3])));
            pnew = (a0 + a1) + (a2 + a3);
            S[j] = pnew;

            // measure stale max (applied 2 iters later), off-chain
            if ((u & 3) == 1) {
                float m0 = fmaxf(fmaxf(q0.x, q0.y), fmaxf(q0.z, q0.w));
                float m1 = fmaxf(fmaxf(q1.x, q1.y), fmaxf(q1.z, q1.w));
                float m2 = fmaxf(fmaxf(q2.x, q2.y), fmaxf(q2.z, q2.w));
                float m3 = fmaxf(fmaxf(q3.x, q3.y), fmaxf(q3.z, q3.w));
                stale_m = fmaxf(fmaxf(m0, m1), fmaxf(m2, m3));
            }

            // next-iteration W = Mr .* ef  (off-chain FMULs)
            W[ 0] = Mr[ 0] * e0.x;  W[ 1] = Mr[ 1] * e0.y;
            W[ 2] = Mr[ 2] * e0.z;  W[ 3] = Mr[ 3] * e0.w;
            W[ 4] = Mr[ 4] * e1.x;  W[ 5] = Mr[ 5] * e1.y;
            W[ 6] = Mr[ 6] * e1.z;  W[ 7] = Mr[ 7] * e1.w;
            W[ 8] = Mr[ 8] * e2.x;  W[ 9] = Mr[ 9] * e2.y;
            W[10] = Mr[10] * e2.z;  W[11] = Mr[11] * e2.w;
            W[12] = Mr[12] * e3.x;  W[13] = Mr[13] * e3.y;
            W[14] = Mr[14] * e3.z;  W[15] = Mr[15] * e3.w;

            // exp for the ef published next iteration (MUFU, off-chain).
            // On the very last iteration this reads a stale fB value whose
            // result is never consumed.
            float fnext = (u < TILE - 1) ? fA[u + 1] : fB[0];
            efn = __expf(fnext);

            // gold score (uniform L1-hot gather + smem lookup, off-chain)
            gold += fbase[(tbase + u) * KTAG + tg] + sLogT[tg * 16 + prevtag];
            prevtag = tg;
        }

        #pragma unroll
        for (int u = 0; u < TILE; u++) { fA[u] = fB[u]; gA[u] = gB[u]; }
    }

    // alpha_T = ef_last .* s_T (s_T = pnew); terminal:
    // forward = esum*ln2 + log( sum_j expT[STOP,j] * ef_last_j * s_T_j )
    float v = Mstop * ef_last * pnew;
    v += __shfl_xor_sync(0xffffffffu, v, 1, 16);
    v += __shfl_xor_sync(0xffffffffu, v, 2, 16);
    v += __shfl_xor_sync(0xffffffffu, v, 4, 16);
    v += __shfl_xor_sync(0xffffffffu, v, 8, 16);

    double fwd = (double)esum * 0.6931471805599453 + (double)__logf(v);
    float goldT = gold + sLogT[STOP_TAG * 16 + prevtag];

    if (lane == 0) out[b] = (float)(fwd - (double)goldT);
}

extern "C" void kernel_launch(void* const* d_in, const int* in_sizes, int n_in,
                              void* d_out, int out_size) {
    const float* feats = (const float*)d_in[0];
    const int*   tags  = (const int*)d_in[1];
    const float* trans = (const float*)d_in[2];
    float* out = (float*)d_out;

    int B = in_sizes[1] / T_LEN;           // 1024
    int blocks = B / 4;                    // 256 blocks x 4 warps, 1 elem/warp
    crf_nll_kernel<<<blocks, 128>>>(feats, tags, trans, out);
}